// round 16
// baseline (speedup 1.0000x reference)
#include <cuda_runtime.h>
#include <cuda_fp16.h>
#include <math.h>
#include <stdint.h>

// ---------------------------------------------------------------------------
// Problem constants
// ---------------------------------------------------------------------------
constexpr int B_   = 16;
constexpr int CIN_ = 128;
constexpr int CM_  = 64;
constexpr int CO_  = 256;
constexpr int N_   = 8192;
constexpr int S_   = 2048;
constexpr int K_   = 16;
constexpr int Q_   = 16;
constexpr int SK_  = S_ * K_;          // 32768

// ---------------------------------------------------------------------------
// Device scratch
// ---------------------------------------------------------------------------
__device__ float  g_h0 [B_ * CM_ * N_];        // raw cv0 output (B,64,N)
__device__ __half g_h0t[B_ * N_ * CM_];        // normalized+relu, transposed fp16
__device__ __half g_sc [B_ * CO_ * N_];        // raw shortcut conv, fp16 (B,256,N)
__device__ float  g_p  [B_ * 3 * S_ * K_];     // normalized local coords (B,3,S,K)
__device__ float  g_dw [B_ * S_ * K_];         // distance weights (B,S,K)
__device__ __half g_agg[B_ * S_ * CM_ * Q_];   // aggregation fp16 (b,s,1024)
__device__ __half g_hf [B_ * CM_ * S_];        // fka output fp16 (B,64,S)
__device__ float  g_y2 [B_ * CO_ * S_];        // cv2 raw (B,256,S)
__device__ float  g_part[1048576];             // stats partials (carved)
__device__ float  g_pm  [128 * 9];             // p-moment partials

// partial-buffer carve (floats)
#define PART_ALL 0         // 320ch x 512seg x 2  (cv0: 0..63, sc: 64..319)
#define PART_Y2  655360    // 256 x 128 x 2
#define PART_Z2  786432    // 256 x 128 x 2
#define PART_HF  851968    // 64 x 256 x 2

// affine params, carved offsets
__device__ float g_aff[2304];
#define OFF_SCALE0   0      // 64
#define OFF_SHIFT0   64
#define OFF_SCALESC  128    // 256
#define OFF_SHIFTSC  384
#define OFF_IN1SC    640    // 256 (b*Q+q)
#define OFF_IN1SH    896
#define OFF_IN2SC    1152
#define OFF_IN2SH    1408
#define OFF_SCALE1   1664   // 64
#define OFF_SHIFT1   1728
#define OFF_SCALE2   1792   // 256
#define OFF_SHIFT2   2048

// ---------------------------------------------------------------------------
// tf32 helpers
// ---------------------------------------------------------------------------
__device__ __forceinline__ uint32_t f2tf32(float v) {
    uint32_t t;
    asm("cvt.rna.tf32.f32 %0, %1;" : "=r"(t) : "f"(v));
    return t;
}

__device__ __forceinline__ void mma_tf32(
    float& c0, float& c1, float& c2, float& c3,
    uint32_t a0, uint32_t a1, uint32_t a2, uint32_t a3,
    uint32_t b0, uint32_t b1)
{
    asm volatile(
        "mma.sync.aligned.m16n8k8.row.col.f32.tf32.tf32.f32 "
        "{%0,%1,%2,%3}, {%4,%5,%6,%7}, {%8,%9}, {%0,%1,%2,%3};"
        : "+f"(c0), "+f"(c1), "+f"(c2), "+f"(c3)
        : "r"(a0), "r"(a1), "r"(a2), "r"(a3), "r"(b0), "r"(b1));
}

// ---------------------------------------------------------------------------
// Dual pointwise conv (cv0 fp32 out + shortcut fp16 out). BN=256.
// z innermost in blockIdx.x for x L2 reuse. 512 segments.
// ---------------------------------------------------------------------------
__global__ void __launch_bounds__(256) pwconv_dual_kernel(
    const float* __restrict__ x,
    const float* __restrict__ w_cv0, const float* __restrict__ b_cv0,
    const float* __restrict__ w_sc,  const float* __restrict__ b_sc,
    float* __restrict__ out_cv0, __half* __restrict__ out_sc,
    float* __restrict__ spart)
{
    constexpr int CIN = 128, BM = 64, BN = 256, BK = 16;
    __shared__ uint32_t xs[BK][BN + 4];
    __shared__ uint32_t ws[BK][BM + 4];
    __shared__ float sred[64][4], qred[64][4];
    const int bx = blockIdx.x;           // 0..159
    const int z  = bx % 5;
    const int nt = bx / 5;               // 0..31
    const int n0 = nt * BN;
    const int b  = blockIdx.y;
    const int o0 = (z == 0) ? 0 : (z - 1) * BM;
    const float* w    = (z == 0) ? w_cv0 : w_sc;
    const float* bias = (z == 0) ? b_cv0 : b_sc;
    const int chbase = (z == 0) ? 0 : 64 + (z - 1) * BM;
    const int tid  = threadIdx.x;
    const int lane = tid & 31, warp = tid >> 5;
    const int wm = warp >> 2, wn = warp & 3;
    const int lg = lane >> 2, lt = lane & 3;

    float acc[2][8][4];
#pragma unroll
    for (int i = 0; i < 2; i++)
#pragma unroll
        for (int j = 0; j < 8; j++)
#pragma unroll
            for (int u = 0; u < 4; u++) acc[i][j][u] = 0.f;

    for (int kc = 0; kc < CIN; kc += BK) {
        __syncthreads();
#pragma unroll
        for (int u = 0; u < 4; u++) {
            int vi = tid + u * 256;
            int k = vi >> 6, c4 = vi & 63;
            float4 v = *(const float4*)&x[((long)b * CIN + kc + k) * N_ + n0 + c4 * 4];
            xs[k][c4 * 4 + 0] = f2tf32(v.x);
            xs[k][c4 * 4 + 1] = f2tf32(v.y);
            xs[k][c4 * 4 + 2] = f2tf32(v.z);
            xs[k][c4 * 4 + 3] = f2tf32(v.w);
        }
        {
            int oo = tid >> 2, k4 = (tid & 3) * 4;
            float4 v = *(const float4*)&w[(long)(o0 + oo) * CIN + kc + k4];
            ws[k4 + 0][oo] = f2tf32(v.x);
            ws[k4 + 1][oo] = f2tf32(v.y);
            ws[k4 + 2][oo] = f2tf32(v.z);
            ws[k4 + 3][oo] = f2tf32(v.w);
        }
        __syncthreads();
#pragma unroll
        for (int kt = 0; kt < BK; kt += 8) {
            uint32_t af[2][4], bf[8][2];
#pragma unroll
            for (int mt = 0; mt < 2; mt++) {
                int rb = wm * 32 + mt * 16 + lg;
                af[mt][0] = ws[kt + lt][rb];
                af[mt][1] = ws[kt + lt][rb + 8];
                af[mt][2] = ws[kt + lt + 4][rb];
                af[mt][3] = ws[kt + lt + 4][rb + 8];
            }
#pragma unroll
            for (int nt2 = 0; nt2 < 8; nt2++) {
                int nb = wn * 64 + nt2 * 8 + lg;
                bf[nt2][0] = xs[kt + lt][nb];
                bf[nt2][1] = xs[kt + lt + 4][nb];
            }
#pragma unroll
            for (int mt = 0; mt < 2; mt++)
#pragma unroll
                for (int nt2 = 0; nt2 < 8; nt2++)
                    mma_tf32(acc[mt][nt2][0], acc[mt][nt2][1],
                             acc[mt][nt2][2], acc[mt][nt2][3],
                             af[mt][0], af[mt][1], af[mt][2], af[mt][3],
                             bf[nt2][0], bf[nt2][1]);
        }
    }
    float rs[2][2] = {{0.f, 0.f}, {0.f, 0.f}};
    float rq[2][2] = {{0.f, 0.f}, {0.f, 0.f}};
#pragma unroll
    for (int mt = 0; mt < 2; mt++) {
        int row0 = o0 + wm * 32 + mt * 16 + lg;
        int row1 = row0 + 8;
        float bv0 = bias[row0], bv1 = bias[row1];
#pragma unroll
        for (int nt2 = 0; nt2 < 8; nt2++) {
            int col = n0 + wn * 64 + nt2 * 8 + lt * 2;
            float v00 = acc[mt][nt2][0] + bv0, v01 = acc[mt][nt2][1] + bv0;
            float v10 = acc[mt][nt2][2] + bv1, v11 = acc[mt][nt2][3] + bv1;
            if (z == 0) {
                *(float2*)&out_cv0[((long)b * CM_ + row0) * N_ + col] = make_float2(v00, v01);
                *(float2*)&out_cv0[((long)b * CM_ + row1) * N_ + col] = make_float2(v10, v11);
            } else {
                *(__half2*)&out_sc[((long)b * CO_ + row0) * N_ + col] = __floats2half2_rn(v00, v01);
                *(__half2*)&out_sc[((long)b * CO_ + row1) * N_ + col] = __floats2half2_rn(v10, v11);
            }
            rs[mt][0] += v00 + v01; rq[mt][0] += v00 * v00 + v01 * v01;
            rs[mt][1] += v10 + v11; rq[mt][1] += v10 * v10 + v11 * v11;
        }
    }
#pragma unroll
    for (int mt = 0; mt < 2; mt++)
#pragma unroll
        for (int h = 0; h < 2; h++) {
#pragma unroll
            for (int off = 1; off <= 2; off <<= 1) {
                rs[mt][h] += __shfl_xor_sync(0xffffffffu, rs[mt][h], off);
                rq[mt][h] += __shfl_xor_sync(0xffffffffu, rq[mt][h], off);
            }
        }
    if (lt == 0) {
#pragma unroll
        for (int mt = 0; mt < 2; mt++)
#pragma unroll
            for (int h = 0; h < 2; h++) {
                int rl = wm * 32 + mt * 16 + lg + h * 8;
                sred[rl][wn] = rs[mt][h];
                qred[rl][wn] = rq[mt][h];
            }
    }
    __syncthreads();
    if (tid < 64) {
        float s = sred[tid][0] + sred[tid][1] + sred[tid][2] + sred[tid][3];
        float q = qred[tid][0] + qred[tid][1] + qred[tid][2] + qred[tid][3];
        int seg = blockIdx.y * 32 + nt;                      // 0..511
        long pi = ((long)(chbase + tid) * 512 + seg) * 2;
        spart[pi + 0] = s;
        spart[pi + 1] = q;
    }
}

// ---------------------------------------------------------------------------
// cv2: BN=256; input hf is fp16, relu(bn1) fused in, bn2 partials fused out.
// ---------------------------------------------------------------------------
__global__ void __launch_bounds__(256) pwconv_cv2_kernel(
    const __half* __restrict__ x, const float* __restrict__ w,
    const float* __restrict__ bias, float* __restrict__ out,
    const float* __restrict__ ns, const float* __restrict__ nt_,
    float* __restrict__ spart)
{
    constexpr int CIN = 64, BM = 64, BN = 256, BK = 16;
    __shared__ uint32_t xs[BK][BN + 4];
    __shared__ uint32_t ws[BK][BM + 4];
    __shared__ float sred[64][4], qred[64][4];
    const int bx = blockIdx.x;           // 0..31
    const int z  = bx & 3;
    const int ntile = bx >> 2;           // 0..7
    const int n0 = ntile * BN;
    const int b  = blockIdx.y;
    const int o0 = z * BM;
    const int tid  = threadIdx.x;
    const int lane = tid & 31, warp = tid >> 5;
    const int wm = warp >> 2, wn = warp & 3;
    const int lg = lane >> 2, lt = lane & 3;

    float acc[2][8][4];
#pragma unroll
    for (int i = 0; i < 2; i++)
#pragma unroll
        for (int j = 0; j < 8; j++)
#pragma unroll
            for (int u = 0; u < 4; u++) acc[i][j][u] = 0.f;

    for (int kc = 0; kc < CIN; kc += BK) {
        __syncthreads();
#pragma unroll
        for (int u = 0; u < 4; u++) {
            int vi = tid + u * 256;
            int k = vi >> 6, c4 = vi & 63;
            uint2 hv = *(const uint2*)&x[((long)b * CIN + kc + k) * S_ + n0 + c4 * 4];
            float2 f0 = __half22float2(*(const __half2*)&hv.x);
            float2 f1 = __half22float2(*(const __half2*)&hv.y);
            float sa = ns[kc + k], sb = nt_[kc + k];
            xs[k][c4 * 4 + 0] = f2tf32(fmaxf(f0.x * sa + sb, 0.f));
            xs[k][c4 * 4 + 1] = f2tf32(fmaxf(f0.y * sa + sb, 0.f));
            xs[k][c4 * 4 + 2] = f2tf32(fmaxf(f1.x * sa + sb, 0.f));
            xs[k][c4 * 4 + 3] = f2tf32(fmaxf(f1.y * sa + sb, 0.f));
        }
        {
            int oo = tid >> 2, k4 = (tid & 3) * 4;
            float4 v = *(const float4*)&w[(long)(o0 + oo) * CIN + kc + k4];
            ws[k4 + 0][oo] = f2tf32(v.x);
            ws[k4 + 1][oo] = f2tf32(v.y);
            ws[k4 + 2][oo] = f2tf32(v.z);
            ws[k4 + 3][oo] = f2tf32(v.w);
        }
        __syncthreads();
#pragma unroll
        for (int kt = 0; kt < BK; kt += 8) {
            uint32_t af[2][4], bf[8][2];
#pragma unroll
            for (int mt = 0; mt < 2; mt++) {
                int rb = wm * 32 + mt * 16 + lg;
                af[mt][0] = ws[kt + lt][rb];
                af[mt][1] = ws[kt + lt][rb + 8];
                af[mt][2] = ws[kt + lt + 4][rb];
                af[mt][3] = ws[kt + lt + 4][rb + 8];
            }
#pragma unroll
            for (int nt2 = 0; nt2 < 8; nt2++) {
                int nb = wn * 64 + nt2 * 8 + lg;
                bf[nt2][0] = xs[kt + lt][nb];
                bf[nt2][1] = xs[kt + lt + 4][nb];
            }
#pragma unroll
            for (int mt = 0; mt < 2; mt++)
#pragma unroll
                for (int nt2 = 0; nt2 < 8; nt2++)
                    mma_tf32(acc[mt][nt2][0], acc[mt][nt2][1],
                             acc[mt][nt2][2], acc[mt][nt2][3],
                             af[mt][0], af[mt][1], af[mt][2], af[mt][3],
                             bf[nt2][0], bf[nt2][1]);
        }
    }
    float rs[2][2] = {{0.f, 0.f}, {0.f, 0.f}};
    float rq[2][2] = {{0.f, 0.f}, {0.f, 0.f}};
#pragma unroll
    for (int mt = 0; mt < 2; mt++) {
        int row0 = o0 + wm * 32 + mt * 16 + lg;
        int row1 = row0 + 8;
        float bv0 = bias[row0], bv1 = bias[row1];
#pragma unroll
        for (int nt2 = 0; nt2 < 8; nt2++) {
            int col = n0 + wn * 64 + nt2 * 8 + lt * 2;
            float v00 = acc[mt][nt2][0] + bv0, v01 = acc[mt][nt2][1] + bv0;
            float v10 = acc[mt][nt2][2] + bv1, v11 = acc[mt][nt2][3] + bv1;
            *(float2*)&out[((long)b * CO_ + row0) * S_ + col] = make_float2(v00, v01);
            *(float2*)&out[((long)b * CO_ + row1) * S_ + col] = make_float2(v10, v11);
            rs[mt][0] += v00 + v01; rq[mt][0] += v00 * v00 + v01 * v01;
            rs[mt][1] += v10 + v11; rq[mt][1] += v10 * v10 + v11 * v11;
        }
    }
#pragma unroll
    for (int mt = 0; mt < 2; mt++)
#pragma unroll
        for (int h = 0; h < 2; h++) {
#pragma unroll
            for (int off = 1; off <= 2; off <<= 1) {
                rs[mt][h] += __shfl_xor_sync(0xffffffffu, rs[mt][h], off);
                rq[mt][h] += __shfl_xor_sync(0xffffffffu, rq[mt][h], off);
            }
        }
    if (lt == 0) {
#pragma unroll
        for (int mt = 0; mt < 2; mt++)
#pragma unroll
            for (int h = 0; h < 2; h++) {
                int rl = wm * 32 + mt * 16 + lg + h * 8;
                sred[rl][wn] = rs[mt][h];
                qred[rl][wn] = rq[mt][h];
            }
    }
    __syncthreads();
    if (tid < 64) {
        float s = sred[tid][0] + sred[tid][1] + sred[tid][2] + sred[tid][3];
        float q = qred[tid][0] + qred[tid][1] + qred[tid][2] + qred[tid][3];
        int seg = blockIdx.y * 8 + ntile;               // 0..127
        long pi = ((long)(o0 + tid) * 128 + seg) * 2;
        spart[pi + 0] = s;
        spart[pi + 1] = q;
    }
}

// ---------------------------------------------------------------------------
// Tensor-core FKA GEMM: hf16[b,o,s] = sum_{r<1024} cv_w[o,r]*agg_fp16[b,s,r]
// fp16 out; bn1 partials from fp32 accumulators (exact).
// ---------------------------------------------------------------------------
__global__ void __launch_bounds__(256) fka_gemm_mma_kernel(
    const __half* __restrict__ A, const float* __restrict__ W,
    __half* __restrict__ out, float* __restrict__ spart)
{
    constexpr int BN = 128, BK = 32;
    __shared__ uint32_t xs[BK][BN + 4];
    __shared__ uint32_t ws[BK][64 + 4];
    __shared__ float sred[64][4], qred[64][4];
    const int s0 = blockIdx.x * BN;
    const int b  = blockIdx.y;
    const int tid  = threadIdx.x;
    const int lane = tid & 31, warp = tid >> 5;
    const int wm = warp >> 2, wn = warp & 3;
    const int lg = lane >> 2, lt = lane & 3;
    const uint32_t* Au = (const uint32_t*)(A + ((long)b * S_ + s0) * 1024);

    float acc[2][4][4];
#pragma unroll
    for (int i = 0; i < 2; i++)
#pragma unroll
        for (int j = 0; j < 4; j++)
#pragma unroll
            for (int u = 0; u < 4; u++) acc[i][j][u] = 0.f;

    const int as  = tid >> 1;             // s index 0..127
    const int ar0 = (tid & 1) * 16;       // r offset within chunk

    for (int rc = 0; rc < 1024; rc += BK) {
        __syncthreads();
        {
            const uint4* src = (const uint4*)&Au[(long)as * 512 + (rc >> 1) + (ar0 >> 1)];
            uint4 v0 = src[0];
            uint4 v1 = src[1];
            uint32_t uu[8] = {v0.x, v0.y, v0.z, v0.w, v1.x, v1.y, v1.z, v1.w};
#pragma unroll
            for (int u = 0; u < 8; u++) {
                float2 f = __half22float2(*(const __half2*)&uu[u]);
                xs[ar0 + u * 2 + 0][as] = f2tf32(f.x);
                xs[ar0 + u * 2 + 1][as] = f2tf32(f.y);
            }
        }
#pragma unroll
        for (int vi = tid; vi < 512; vi += 256) {
            int o = vi >> 3, r4 = (vi & 7) * 4;
            float4 v = *(const float4*)&W[(long)o * 1024 + rc + r4];
            ws[r4 + 0][o] = f2tf32(v.x);
            ws[r4 + 1][o] = f2tf32(v.y);
            ws[r4 + 2][o] = f2tf32(v.z);
            ws[r4 + 3][o] = f2tf32(v.w);
        }
        __syncthreads();
#pragma unroll
        for (int kt = 0; kt < BK; kt += 8) {
            uint32_t af[2][4], bf[4][2];
#pragma unroll
            for (int mt = 0; mt < 2; mt++) {
                int rb = wm * 32 + mt * 16 + lg;
                af[mt][0] = ws[kt + lt][rb];
                af[mt][1] = ws[kt + lt][rb + 8];
                af[mt][2] = ws[kt + lt + 4][rb];
                af[mt][3] = ws[kt + lt + 4][rb + 8];
            }
#pragma unroll
            for (int nt2 = 0; nt2 < 4; nt2++) {
                int nb = wn * 32 + nt2 * 8 + lg;
                bf[nt2][0] = xs[kt + lt][nb];
                bf[nt2][1] = xs[kt + lt + 4][nb];
            }
#pragma unroll
            for (int mt = 0; mt < 2; mt++)
#pragma unroll
                for (int nt2 = 0; nt2 < 4; nt2++)
                    mma_tf32(acc[mt][nt2][0], acc[mt][nt2][1],
                             acc[mt][nt2][2], acc[mt][nt2][3],
                             af[mt][0], af[mt][1], af[mt][2], af[mt][3],
                             bf[nt2][0], bf[nt2][1]);
        }
    }
    // epilogue (fp16 out) + fused bn1 partials (fp32 accs)
    float rs[2][2] = {{0.f, 0.f}, {0.f, 0.f}};
    float rq[2][2] = {{0.f, 0.f}, {0.f, 0.f}};
#pragma unroll
    for (int mt = 0; mt < 2; mt++) {
        int row0 = wm * 32 + mt * 16 + lg;
        int row1 = row0 + 8;
#pragma unroll
        for (int nt2 = 0; nt2 < 4; nt2++) {
            int col = s0 + wn * 32 + nt2 * 8 + lt * 2;
            float v00 = acc[mt][nt2][0], v01 = acc[mt][nt2][1];
            float v10 = acc[mt][nt2][2], v11 = acc[mt][nt2][3];
            *(__half2*)&out[((long)b * 64 + row0) * S_ + col] = __floats2half2_rn(v00, v01);
            *(__half2*)&out[((long)b * 64 + row1) * S_ + col] = __floats2half2_rn(v10, v11);
            rs[mt][0] += v00 + v01; rq[mt][0] += v00 * v00 + v01 * v01;
            rs[mt][1] += v10 + v11; rq[mt][1] += v10 * v10 + v11 * v11;
        }
    }
#pragma unroll
    for (int mt = 0; mt < 2; mt++)
#pragma unroll
        for (int h = 0; h < 2; h++) {
#pragma unroll
            for (int off = 1; off <= 2; off <<= 1) {
                rs[mt][h] += __shfl_xor_sync(0xffffffffu, rs[mt][h], off);
                rq[mt][h] += __shfl_xor_sync(0xffffffffu, rq[mt][h], off);
            }
        }
    if (lt == 0) {
#pragma unroll
        for (int mt = 0; mt < 2; mt++)
#pragma unroll
            for (int h = 0; h < 2; h++) {
                int rl = wm * 32 + mt * 16 + lg + h * 8;
                sred[rl][wn] = rs[mt][h];
                qred[rl][wn] = rq[mt][h];
            }
    }
    __syncthreads();
    if (tid < 64) {
        float s = sred[tid][0] + sred[tid][1] + sred[tid][2] + sred[tid][3];
        float q = qred[tid][0] + qred[tid][1] + qred[tid][2] + qred[tid][3];
        int nseg = gridDim.x * gridDim.y;               // 256
        int seg  = blockIdx.y * gridDim.x + blockIdx.x;
        long pi = ((long)tid * nseg + seg) * 2;
        spart[pi + 0] = s;
        spart[pi + 1] = q;
    }
}

// ---------------------------------------------------------------------------
// Stats finalize
// ---------------------------------------------------------------------------
__global__ void __launch_bounds__(128) stats_final_kernel(
    const float* __restrict__ partial, int nseg, float M,
    const float* __restrict__ g, const float* __restrict__ bb, int gmod,
    float* __restrict__ scale, float* __restrict__ shift)
{
    const int c = blockIdx.x;
    float ls = 0.f, lq = 0.f;
    for (int i = threadIdx.x; i < nseg; i += 128) {
        ls += partial[(c * nseg + i) * 2 + 0];
        lq += partial[(c * nseg + i) * 2 + 1];
    }
#pragma unroll
    for (int off = 16; off; off >>= 1) {
        ls += __shfl_xor_sync(0xffffffffu, ls, off);
        lq += __shfl_xor_sync(0xffffffffu, lq, off);
    }
    __shared__ float sh[8];
    const int wid = threadIdx.x >> 5, lane = threadIdx.x & 31;
    if (lane == 0) { sh[wid] = ls; sh[4 + wid] = lq; }
    __syncthreads();
    if (threadIdx.x == 0) {
        float ts = sh[0] + sh[1] + sh[2] + sh[3];
        float tq = sh[4] + sh[5] + sh[6] + sh[7];
        float mean = ts / M;
        float var  = tq / M - mean * mean;
        float sc = g[c % gmod] * rsqrtf(var + 1e-5f);
        scale[c] = sc;
        shift[c] = bb[c % gmod] - mean * sc;
    }
}

// ---------------------------------------------------------------------------
// Merged finals: bn0 (blk 0..63), bnsc (64..319) over 512 segs,
// in1-from-moments (320..575)
// ---------------------------------------------------------------------------
__global__ void __launch_bounds__(128) finals_merged_kernel(
    const float* __restrict__ part, const float* __restrict__ pm,
    const float* __restrict__ w1,
    const float* __restrict__ bn0_g, const float* __restrict__ bn0_b,
    const float* __restrict__ bnsc_g, const float* __restrict__ bnsc_b,
    const float* __restrict__ in1_g, const float* __restrict__ in1_b,
    float* __restrict__ aff)
{
    const int blk = blockIdx.x;
    if (blk < 320) {
        const int c = blk;
        float ls = 0.f, lq = 0.f;
        for (int i = threadIdx.x; i < 512; i += 128) {
            ls += part[(c * 512 + i) * 2 + 0];
            lq += part[(c * 512 + i) * 2 + 1];
        }
#pragma unroll
        for (int off = 16; off; off >>= 1) {
            ls += __shfl_xor_sync(0xffffffffu, ls, off);
            lq += __shfl_xor_sync(0xffffffffu, lq, off);
        }
        __shared__ float sh[8];
        const int wid = threadIdx.x >> 5, lane = threadIdx.x & 31;
        if (lane == 0) { sh[wid] = ls; sh[4 + wid] = lq; }
        __syncthreads();
        if (threadIdx.x == 0) {
            float ts = sh[0] + sh[1] + sh[2] + sh[3];
            float tq = sh[4] + sh[5] + sh[6] + sh[7];
            float M = (float)B_ * (float)N_;
            float mean = ts / M;
            float var  = tq / M - mean * mean;
            if (c < 64) {
                float sc = bn0_g[c] * rsqrtf(var + 1e-5f);
                aff[OFF_SCALE0 + c] = sc;
                aff[OFF_SHIFT0 + c] = bn0_b[c] - mean * sc;
            } else {
                int cc = c - 64;
                float sc = bnsc_g[cc] * rsqrtf(var + 1e-5f);
                aff[OFF_SCALESC + cc] = sc;
                aff[OFF_SHIFTSC + cc] = bnsc_b[cc] - mean * sc;
            }
        }
    } else {
        const int bq = blk - 320;
        const int b = bq >> 4, q = bq & 15;
        if (threadIdx.x < 32) {
            const int lane = threadIdx.x;
            float v = 0.f;
            if (lane < 9)
                for (int i = 0; i < 8; i++) v += pm[(b * 8 + i) * 9 + lane];
            float m[9];
#pragma unroll
            for (int j = 0; j < 9; j++) m[j] = __shfl_sync(0xffffffffu, v, j);
            if (lane == 0) {
                const float Mv = (float)SK_;
                float w0 = w1[q * 3 + 0], wa = w1[q * 3 + 1], wb = w1[q * 3 + 2];
                float mu = (w0 * m[0] + wa * m[1] + wb * m[2]) / Mv;
                float e2 = (w0 * w0 * m[3] + 2.f * w0 * wa * m[4] + 2.f * w0 * wb * m[5]
                          + wa * wa * m[6] + 2.f * wa * wb * m[7] + wb * wb * m[8]) / Mv;
                float var = e2 - mu * mu;
                float sc = in1_g[q] * rsqrtf(var + 1e-5f);
                aff[OFF_IN1SC + bq] = sc;
                aff[OFF_IN1SH + bq] = in1_b[q] - mu * sc;
            }
        }
    }
}

// ---------------------------------------------------------------------------
// Normalize+relu h0 and transpose to (B,N,64) fp16; 64x64 tiles
// ---------------------------------------------------------------------------
__global__ void __launch_bounds__(256) transpose_norm_kernel(
    const float* __restrict__ in, __half* __restrict__ outT,
    const float* __restrict__ scale, const float* __restrict__ shift)
{
    __shared__ float t[64][65];
    const int n0 = blockIdx.x * 64;
    const int b  = blockIdx.y;
    const int tid = threadIdx.x;
#pragma unroll
    for (int i = tid; i < 1024; i += 256) {
        int c = i >> 4, n4 = (i & 15) * 4;
        float4 v = *(const float4*)&in[((long)b * 64 + c) * N_ + n0 + n4];
        float sa = scale[c], sb = shift[c];
        t[c][n4 + 0] = fmaxf(v.x * sa + sb, 0.f);
        t[c][n4 + 1] = fmaxf(v.y * sa + sb, 0.f);
        t[c][n4 + 2] = fmaxf(v.z * sa + sb, 0.f);
        t[c][n4 + 3] = fmaxf(v.w * sa + sb, 0.f);
    }
    __syncthreads();
#pragma unroll
    for (int i = tid; i < 1024; i += 256) {
        int n = i >> 4, c4 = (i & 15) * 4;
        __half2 h0v = __floats2half2_rn(t[c4][n], t[c4 + 1][n]);
        __half2 h1v = __floats2half2_rn(t[c4 + 2][n], t[c4 + 3][n]);
        uint2 u = make_uint2(*(uint32_t*)&h0v, *(uint32_t*)&h1v);
        *(uint2*)&outT[((long)b * N_ + n0 + n) * 64 + c4] = u;
    }
}

// ---------------------------------------------------------------------------
// FKA prep: local coords p + dw, per-block p-moment partials
// ---------------------------------------------------------------------------
__global__ void __launch_bounds__(256) fka_prep_kernel(
    const float* __restrict__ pos, const float* __restrict__ sup,
    const int* __restrict__ idx, const float* __restrict__ alpha,
    const float* __restrict__ beta, const float* __restrict__ nr,
    float* __restrict__ p, float* __restrict__ dw, float* __restrict__ pm)
{
    int t = blockIdx.x * blockDim.x + threadIdx.x;
    int b = t / S_, s = t % S_;
    float a = alpha[0], be = beta[0], inr = 1.f / nr[0];
    float sx = sup[((long)b * 3 + 0) * S_ + s];
    float sy = sup[((long)b * 3 + 1) * S_ + s];
    float sz = sup[((long)b * 3 + 2) * S_ + s];
    float dwl[K_];
    float sum = 0.f;
    float mm[9];
#pragma unroll
    for (int j = 0; j < 9; j++) mm[j] = 0.f;
#pragma unroll
    for (int k = 0; k < K_; k++) {
        int id = idx[(long)t * K_ + k];
        float px = pos[((long)b * 3 + 0) * N_ + id] - sx;
        float py = pos[((long)b * 3 + 1) * N_ + id] - sy;
        float pz = pos[((long)b * 3 + 2) * N_ + id] - sz;
        float d = sqrtf(px * px + py * py + pz * pz);
        float wv = 1.f / (1.f + expf(a * d - be));
        dwl[k] = wv; sum += wv;
        float n0v = px * inr, n1v = py * inr, n2v = pz * inr;
        long eb = (long)s * K_ + k;
        p[((long)b * 3 + 0) * SK_ + eb] = n0v;
        p[((long)b * 3 + 1) * SK_ + eb] = n1v;
        p[((long)b * 3 + 2) * SK_ + eb] = n2v;
        mm[0] += n0v; mm[1] += n1v; mm[2] += n2v;
        mm[3] += n0v * n0v; mm[4] += n0v * n1v; mm[5] += n0v * n2v;
        mm[6] += n1v * n1v; mm[7] += n1v * n2v; mm[8] += n2v * n2v;
    }
    sum = sum + (sum == 0.f ? 1.f : 0.f) + 1e-6f;
    float f = (float)K_ / sum;
#pragma unroll
    for (int k = 0; k < K_; k++) dw[(long)t * K_ + k] = dwl[k] * f;

    __shared__ float sm[8][9];
    const int wid = threadIdx.x >> 5, lane = threadIdx.x & 31;
#pragma unroll
    for (int j = 0; j < 9; j++) {
        float v = mm[j];
#pragma unroll
        for (int off = 16; off; off >>= 1)
            v += __shfl_xor_sync(0xffffffffu, v, off);
        if (lane == 0) sm[wid][j] = v;
    }
    __syncthreads();
    if (threadIdx.x < 9) {
        float v = 0.f;
#pragma unroll
        for (int w = 0; w < 8; w++) v += sm[w][threadIdx.x];
        pm[blockIdx.x * 9 + threadIdx.x] = v;
    }
}

// ---------------------------------------------------------------------------
// Stage 2 (stats only): z1 on the fly; z2 computed but NOT stored;
// emits IN2 stats partials.
// ---------------------------------------------------------------------------
__global__ void __launch_bounds__(256) fc_stage2_kernel(
    const float* __restrict__ p, const float* __restrict__ w1,
    const float* __restrict__ w2,
    const float* __restrict__ sc1, const float* __restrict__ sh1,
    const float* __restrict__ dw, float* __restrict__ spart)
{
    __shared__ float w2s[16 * 32];
    __shared__ float w1s[48];
    __shared__ float scs[16], shs[16];
    __shared__ float sred[8][16], qred[8][16];
    const int tid = threadIdx.x;
    const int b = blockIdx.x >> 7;
    const int s0 = (blockIdx.x & 127) * 16;
    const int g = tid >> 4, lane = tid & 15;
    const int warp = tid >> 5, wlane = tid & 31;
    const int s = s0 + g;

    w2s[tid] = w2[tid];
    w2s[tid + 256] = w2[tid + 256];
    if (tid < 48) w1s[tid] = w1[tid];
    if (tid < 16) { scs[tid] = sc1[b * 16 + tid]; shs[tid] = sh1[b * 16 + tid]; }
    __syncthreads();

    const long e = (long)s * K_ + lane;
    const float p0 = p[((long)b * 3 + 0) * SK_ + e];
    const float p1 = p[((long)b * 3 + 1) * SK_ + e];
    const float p2 = p[((long)b * 3 + 2) * SK_ + e];
    const float dwk = dw[((long)b * S_ + s) * K_ + lane];
    float m[32];
#pragma unroll
    for (int q = 0; q < 16; q++) {
        float z = w1s[q * 3 + 0] * p0 + w1s[q * 3 + 1] * p1 + w1s[q * 3 + 2] * p2;
        float v = fmaxf(z * scs[q] + shs[q], 0.f);
        m[q] = v;
        float md = v * dwk;
#pragma unroll
        for (int off = 8; off; off >>= 1)
            md = fmaxf(md, __shfl_xor_sync(0xffffffffu, md, off, 16));
        m[16 + q] = md;
    }
#pragma unroll
    for (int q2 = 0; q2 < 16; q2++) {
        float acc = 0.f;
#pragma unroll
        for (int c = 0; c < 32; c++) acc += w2s[q2 * 32 + c] * m[c];
        float a1 = acc, a2 = acc * acc;
#pragma unroll
        for (int off = 16; off; off >>= 1) {
            a1 += __shfl_xor_sync(0xffffffffu, a1, off);
            a2 += __shfl_xor_sync(0xffffffffu, a2, off);
        }
        if (wlane == 0) { sred[warp][q2] = a1; qred[warp][q2] = a2; }
    }
    __syncthreads();
    if (tid < 16) {
        float s1 = 0.f, s2 = 0.f;
#pragma unroll
        for (int w = 0; w < 8; w++) { s1 += sred[w][tid]; s2 += qred[w][tid]; }
        int ch = b * 16 + tid;
        int seg = blockIdx.x & 127;
        spart[(ch * 128 + seg) * 2 + 0] = s1;
        spart[(ch * 128 + seg) * 2 + 1] = s2;
    }
}

// ---------------------------------------------------------------------------
// Stage 3 + aggregation (recomputes z1/z2 from p, bit-exact vs stage 2)
// fp16 h0t gather, fp16 agg output.
// ---------------------------------------------------------------------------
__global__ void __launch_bounds__(256) fc_stage3_agg_kernel(
    const float* __restrict__ p, const float* __restrict__ w1,
    const float* __restrict__ w2, const float* __restrict__ w3,
    const float* __restrict__ sc1, const float* __restrict__ sh1,
    const float* __restrict__ sc2, const float* __restrict__ sh2,
    const float* __restrict__ dw, const int* __restrict__ idx,
    const __half* __restrict__ h0t, __half* __restrict__ agg)
{
    __shared__ float w2s[512];
    __shared__ float w3s[512];
    __shared__ float w1s[48];
    __shared__ float sc1s[16], sh1s[16], sc2s[16], sh2s[16];
    __shared__ float smat[16][16][16];   // [group][q][k]
    __shared__ int   sidx[16][16];
    const int tid = threadIdx.x;
    const int b = blockIdx.x >> 7;
    const int s0 = (blockIdx.x & 127) * 16;
    const int g = tid >> 4, lane = tid & 15;
    const int s = s0 + g;

    w2s[tid] = w2[tid];
    w2s[tid + 256] = w2[tid + 256];
    w3s[tid] = w3[tid];
    w3s[tid + 256] = w3[tid + 256];
    if (tid < 48) w1s[tid] = w1[tid];
    if (tid < 16) {
        sc1s[tid] = sc1[b * 16 + tid]; sh1s[tid] = sh1[b * 16 + tid];
        sc2s[tid] = sc2[b * 16 + tid]; sh2s[tid] = sh2[b * 16 + tid];
    }
    __syncthreads();

    const long e = (long)s * K_ + lane;
    const float p0 = p[((long)b * 3 + 0) * SK_ + e];
    const float p1 = p[((long)b * 3 + 1) * SK_ + e];
    const float p2 = p[((long)b * 3 + 2) * SK_ + e];
    const float dwk = dw[((long)b * S_ + s) * K_ + lane];
    sidx[g][lane] = idx[((long)b * S_ + s) * K_ + lane];

    float m1[32];
#pragma unroll
    for (int q = 0; q < 16; q++) {
        float z = w1s[q * 3 + 0] * p0 + w1s[q * 3 + 1] * p1 + w1s[q * 3 + 2] * p2;
        float v = fmaxf(z * sc1s[q] + sh1s[q], 0.f);
        m1[q] = v;
        float md = v * dwk;
#pragma unroll
        for (int off = 8; off; off >>= 1)
            md = fmaxf(md, __shfl_xor_sync(0xffffffffu, md, off, 16));
        m1[16 + q] = md;
    }
    float m2[32];
#pragma unroll
    for (int q2 = 0; q2 < 16; q2++) {
        float acc = 0.f;
#pragma unroll
        for (int c = 0; c < 32; c++) acc += w2s[q2 * 32 + c] * m1[c];
        float v = fmaxf(acc * sc2s[q2] + sh2s[q2], 0.f);
        m2[q2] = v;
        float md = v * dwk;
#pragma unroll
        for (int off = 8; off; off >>= 1)
            md = fmaxf(md, __shfl_xor_sync(0xffffffffu, md, off, 16));
        m2[16 + q2] = md;
    }
#pragma unroll
    for (int q3 = 0; q3 < 16; q3++) {
        float acc = 0.f;
#pragma unroll
        for (int c = 0; c < 32; c++) acc += w3s[q3 * 32 + c] * m2[c];
        smat[g][q3][lane] = fmaxf(acc, 0.f) * dwk;
    }
    __syncwarp();

    float acc2[4][16];
#pragma unroll
    for (int cu = 0; cu < 4; cu++)
#pragma unroll
        for (int q = 0; q < 16; q++) acc2[cu][q] = 0.f;

#pragma unroll
    for (int k = 0; k < 16; k++) {
        int id = sidx[g][k];
        uint2 hv = *(const uint2*)(h0t + ((long)b * N_ + id) * 64 + lane * 4);
        float2 f0 = __half22float2(*(const __half2*)&hv.x);
        float2 f1 = __half22float2(*(const __half2*)&hv.y);
#pragma unroll
        for (int q = 0; q < 16; q++) {
            float mv = smat[g][q][k];
            acc2[0][q] += f0.x * mv;
            acc2[1][q] += f0.y * mv;
            acc2[2][q] += f1.x * mv;
            acc2[3][q] += f1.y * mv;
        }
    }
    uint32_t* aggu = (uint32_t*)agg;
    long base = ((long)b * S_ + s) * 512 + lane * 32;
#pragma unroll
    for (int cu = 0; cu < 4; cu++) {
        uint32_t pk[8];
#pragma unroll
        for (int qq = 0; qq < 8; qq++) {
            __half2 h2 = __floats2half2_rn(acc2[cu][qq * 2], acc2[cu][qq * 2 + 1]);
            pk[qq] = *(uint32_t*)&h2;
        }
        *(uint4*)&aggu[base + cu * 8 + 0] = make_uint4(pk[0], pk[1], pk[2], pk[3]);
        *(uint4*)&aggu[base + cu * 8 + 4] = make_uint4(pk[4], pk[5], pk[6], pk[7]);
    }
}

// ---------------------------------------------------------------------------
// Final fuse: out[b,o,s] = relu( bn2(y2)[b,o,s] + bnsc(gather-max sc16) )
// ---------------------------------------------------------------------------
__global__ void __launch_bounds__(256) final_fuse_kernel(
    const float* __restrict__ y2, const __half* __restrict__ ysc,
    const int* __restrict__ idx, const float* __restrict__ s2,
    const float* __restrict__ t2, const float* __restrict__ ssc,
    const float* __restrict__ tsc, float* __restrict__ out)
{
    __shared__ __half row[N_];
    const int o = blockIdx.x, b = blockIdx.y;
    const __half* src = ysc + ((long)b * CO_ + o) * N_;
    {
        const uint4* s4 = (const uint4*)src;
        uint4* d4 = (uint4*)row;
        for (int i = threadIdx.x; i < 1024; i += 256) d4[i] = s4[i];
    }
    __syncthreads();
    const float sa = ssc[o], sb = tsc[o];
    const float ha = s2[o],  hb = t2[o];
    const int* ib = idx + (long)b * S_ * K_;
    const float* y2b = y2 + ((long)b * CO_ + o) * S_;
    float* ob = out + ((long)b * CO_ + o) * S_;
    for (int s = threadIdx.x; s < S_; s += 256) {
        const int4* ip = (const int4*)(ib + s * K_);
        float mx = -1e30f, mn = 1e30f;
#pragma unroll
        for (int kk = 0; kk < 4; kk++) {
            int4 v = ip[kk];
            float a = __half2float(row[v.x]);
            float c = __half2float(row[v.y]);
            float d = __half2float(row[v.z]);
            float e = __half2float(row[v.w]);
            mx = fmaxf(fmaxf(fmaxf(mx, a), fmaxf(c, d)), e);
            mn = fminf(fminf(fminf(mn, a), fminf(c, d)), e);
        }
        float scv = (sa >= 0.f) ? (sa * mx + sb) : (sa * mn + sb);
        ob[s] = fmaxf(y2b[s] * ha + hb + scv, 0.f);
    }
}

// ---------------------------------------------------------------------------
// Host launcher
// ---------------------------------------------------------------------------
extern "C" void kernel_launch(void* const* d_in, const int* in_sizes, int n_in,
                              void* d_out, int out_size)
{
    const float* x      = (const float*)d_in[0];
    const float* pos    = (const float*)d_in[1];
    const float* sup    = (const float*)d_in[2];
    const int*   idx    = (const int*)  d_in[3];
    // d_in[4] = mask_indices (unused)
    const float* cv0_w  = (const float*)d_in[5];
    const float* cv0_b  = (const float*)d_in[6];
    const float* bn0_g  = (const float*)d_in[7];
    const float* bn0_b  = (const float*)d_in[8];
    const float* fc1_w  = (const float*)d_in[9];
    const float* fc2_w  = (const float*)d_in[10];
    const float* fc3_w  = (const float*)d_in[11];
    const float* in1_g  = (const float*)d_in[12];
    const float* in1_b  = (const float*)d_in[13];
    const float* in2_g  = (const float*)d_in[14];
    const float* in2_b  = (const float*)d_in[15];
    const float* alpha  = (const float*)d_in[16];
    const float* beta   = (const float*)d_in[17];
    const float* nrad   = (const float*)d_in[18];
    const float* cv_w   = (const float*)d_in[19];
    const float* bn1_g  = (const float*)d_in[20];
    const float* bn1_b  = (const float*)d_in[21];
    const float* cv2_w  = (const float*)d_in[22];
    const float* cv2_b  = (const float*)d_in[23];
    const float* bn2_g  = (const float*)d_in[24];
    const float* bn2_b  = (const float*)d_in[25];
    const float* sc_w   = (const float*)d_in[26];
    const float* sc_b   = (const float*)d_in[27];
    const float* bnsc_g = (const float*)d_in[28];
    const float* bnsc_b = (const float*)d_in[29];
    float* out = (float*)d_out;

    float *p_h0, *p_p, *p_dw, *p_y2, *p_aff, *p_part, *p_pm;
    __half *p_h0t, *p_agg, *p_sc, *p_hf;
    cudaGetSymbolAddress((void**)&p_h0,  g_h0);
    cudaGetSymbolAddress((void**)&p_h0t, g_h0t);
    cudaGetSymbolAddress((void**)&p_sc,  g_sc);
    cudaGetSymbolAddress((void**)&p_p,   g_p);
    cudaGetSymbolAddress((void**)&p_dw,  g_dw);
    cudaGetSymbolAddress((void**)&p_agg, g_agg);
    cudaGetSymbolAddress((void**)&p_hf,  g_hf);
    cudaGetSymbolAddress((void**)&p_y2,  g_y2);
    cudaGetSymbolAddress((void**)&p_aff, g_aff);
    cudaGetSymbolAddress((void**)&p_part, g_part);
    cudaGetSymbolAddress((void**)&p_pm,  g_pm);

    // 1) cv0 (fp32) + shortcut (fp16) convs
    pwconv_dual_kernel<<<dim3(160, B_), 256>>>(
        x, cv0_w, cv0_b, sc_w, sc_b, p_h0, p_sc, p_part + PART_ALL);

    // 2) FKA geometry prep (+ p-moment partials)
    fka_prep_kernel<<<(B_ * S_) / 256, 256>>>(pos, sup, idx, alpha, beta, nrad,
                                              p_p, p_dw, p_pm);

    // 3) merged finals: bn0, bnsc, IN1-from-moments
    finals_merged_kernel<<<576, 128>>>(p_part + PART_ALL, p_pm, fc1_w,
        bn0_g, bn0_b, bnsc_g, bnsc_b, in1_g, in1_b, p_aff);

    // 4) normalize+relu+transpose h0 -> (B,N,64) fp16
    transpose_norm_kernel<<<dim3(N_/64, B_), 256>>>(
        p_h0, p_h0t, p_aff + OFF_SCALE0, p_aff + OFF_SHIFT0);

    // 5) stage 2 (stats-only)
    fc_stage2_kernel<<<(B_ * S_) / 16, 256>>>(p_p, fc1_w, fc2_w,
        p_aff + OFF_IN1SC, p_aff + OFF_IN1SH, p_dw, p_part + PART_Z2);
    stats_final_kernel<<<256, 128>>>(p_part + PART_Z2, 128, (float)SK_,
        in2_g, in2_b, Q_, p_aff + OFF_IN2SC, p_aff + OFF_IN2SH);

    // 6) stage 3 + aggregation (fp16 h0t gather, fp16 agg)
    fc_stage3_agg_kernel<<<(B_ * S_) / 16, 256>>>(p_p, fc1_w, fc2_w, fc3_w,
        p_aff + OFF_IN1SC, p_aff + OFF_IN1SH,
        p_aff + OFF_IN2SC, p_aff + OFF_IN2SH, p_dw, idx, p_h0t, p_agg);

    // 7) final FKA contraction (tf32 MMA, fp16 in/out) + fused bn1 partials
    fka_gemm_mma_kernel<<<dim3(S_/128, B_), 256>>>(p_agg, cv_w, p_hf,
        p_part + PART_HF);
    stats_final_kernel<<<CM_, 128>>>(p_part + PART_HF, 256, (float)(B_ * S_),
        bn1_g, bn1_b, CM_, p_aff + OFF_SCALE1, p_aff + OFF_SHIFT1);

    // 8) cv2 (fp16 hf input)
    pwconv_cv2_kernel<<<dim3(32, B_), 256>>>(
        p_hf, cv2_w, cv2_b, p_y2, p_aff + OFF_SCALE1, p_aff + OFF_SHIFT1,
        p_part + PART_Y2);
    stats_final_kernel<<<CO_, 128>>>(p_part + PART_Y2, 128, (float)(B_ * S_),
        bn2_g, bn2_b, CO_, p_aff + OFF_SCALE2, p_aff + OFF_SHIFT2);

    // 9) final fuse
    final_fuse_kernel<<<dim3(CO_, B_), 256>>>(p_y2, p_sc, idx,
        p_aff + OFF_SCALE2, p_aff + OFF_SHIFT2,
        p_aff + OFF_SCALESC, p_aff + OFF_SHIFTSC, out);
}

// round 17
// speedup vs baseline: 1.0668x; 1.0668x over previous
#include <cuda_runtime.h>
#include <cuda_fp16.h>
#include <math.h>
#include <stdint.h>

// ---------------------------------------------------------------------------
// Problem constants
// ---------------------------------------------------------------------------
constexpr int B_   = 16;
constexpr int CIN_ = 128;
constexpr int CM_  = 64;
constexpr int CO_  = 256;
constexpr int N_   = 8192;
constexpr int S_   = 2048;
constexpr int K_   = 16;
constexpr int Q_   = 16;
constexpr int SK_  = S_ * K_;          // 32768

// ---------------------------------------------------------------------------
// Device scratch
// ---------------------------------------------------------------------------
__device__ float  g_h0 [B_ * CM_ * N_];        // raw cv0 output (B,64,N)
__device__ __half g_h0t[B_ * N_ * CM_];        // normalized+relu, transposed fp16
__device__ __half g_sc [B_ * CO_ * N_];        // raw shortcut conv, fp16 (B,256,N)
__device__ float  g_p  [B_ * 3 * S_ * K_];     // normalized local coords (B,3,S,K)
__device__ float  g_dw [B_ * S_ * K_];         // distance weights (B,S,K)
__device__ __half g_agg[B_ * S_ * CM_ * Q_];   // aggregation fp16 (b,s,1024)
__device__ __half g_hf [B_ * CM_ * S_];        // fka output fp16 (B,64,S)
__device__ float  g_y2 [B_ * CO_ * S_];        // cv2 raw (B,256,S)
__device__ float  g_part[1048576];             // stats partials (carved)
__device__ float  g_pm  [128 * 9];             // p-moment partials

// partial-buffer carve (floats)
#define PART_ALL 0         // 320ch x 512seg x 2  (cv0: 0..63, sc: 64..319)
#define PART_Y2  655360    // 256 x 128 x 2
#define PART_Z2  786432    // 256 x 128 x 2
#define PART_HF  851968    // 64 x 256 x 2

// affine params, carved offsets
__device__ float g_aff[2304];
#define OFF_SCALE0   0      // 64
#define OFF_SHIFT0   64
#define OFF_SCALESC  128    // 256
#define OFF_SHIFTSC  384
#define OFF_IN1SC    640    // 256 (b*Q+q)
#define OFF_IN1SH    896
#define OFF_IN2SC    1152
#define OFF_IN2SH    1408
#define OFF_SCALE1   1664   // 64
#define OFF_SHIFT1   1728
#define OFF_SCALE2   1792   // 256
#define OFF_SHIFT2   2048

// ---------------------------------------------------------------------------
// fp16 MMA helper: D(16x8,f32) += A(16x16,f16,row) * B(16x8,f16,col)
// ---------------------------------------------------------------------------
__device__ __forceinline__ void mma_f16(
    float& c0, float& c1, float& c2, float& c3,
    uint32_t a0, uint32_t a1, uint32_t a2, uint32_t a3,
    uint32_t b0, uint32_t b1)
{
    asm volatile(
        "mma.sync.aligned.m16n8k16.row.col.f32.f16.f16.f32 "
        "{%0,%1,%2,%3}, {%4,%5,%6,%7}, {%8,%9}, {%0,%1,%2,%3};"
        : "+f"(c0), "+f"(c1), "+f"(c2), "+f"(c3)
        : "r"(a0), "r"(a1), "r"(a2), "r"(a3), "r"(b0), "r"(b1));
}

// ---------------------------------------------------------------------------
// Dual pointwise conv (cv0 fp32 out + shortcut fp16 out), fp16 MMA.
// BN=256; smem layouts: xs[n][k] stride 18 halves, ws[o][k] stride 20 halves.
// ---------------------------------------------------------------------------
__global__ void __launch_bounds__(256) pwconv_dual_kernel(
    const float* __restrict__ x,
    const float* __restrict__ w_cv0, const float* __restrict__ b_cv0,
    const float* __restrict__ w_sc,  const float* __restrict__ b_sc,
    float* __restrict__ out_cv0, __half* __restrict__ out_sc,
    float* __restrict__ spart)
{
    constexpr int CIN = 128, BM = 64, BN = 256, BK = 16;
    __shared__ __half xs[BN * 18];
    __shared__ __half ws[BM * 20];
    __shared__ float sred[64][4], qred[64][4];
    const int bx = blockIdx.x;           // 0..159
    const int z  = bx % 5;
    const int nt = bx / 5;               // 0..31
    const int n0 = nt * BN;
    const int b  = blockIdx.y;
    const int o0 = (z == 0) ? 0 : (z - 1) * BM;
    const float* w    = (z == 0) ? w_cv0 : w_sc;
    const float* bias = (z == 0) ? b_cv0 : b_sc;
    const int chbase = (z == 0) ? 0 : 64 + (z - 1) * BM;
    const int tid  = threadIdx.x;
    const int lane = tid & 31, warp = tid >> 5;
    const int wm = warp >> 2, wn = warp & 3;
    const int lg = lane >> 2, lt = lane & 3;

    float acc[2][8][4];
#pragma unroll
    for (int i = 0; i < 2; i++)
#pragma unroll
        for (int j = 0; j < 8; j++)
#pragma unroll
            for (int u = 0; u < 4; u++) acc[i][j][u] = 0.f;

    for (int kc = 0; kc < CIN; kc += BK) {
        __syncthreads();
        // x tile: scatter to xs[n][k]
#pragma unroll
        for (int u = 0; u < 4; u++) {
            int vi = tid + u * 256;
            int k = vi >> 6, c4 = vi & 63;
            float4 v = *(const float4*)&x[((long)b * CIN + kc + k) * N_ + n0 + c4 * 4];
            int nb = c4 * 4;
            xs[(nb + 0) * 18 + k] = __float2half_rn(v.x);
            xs[(nb + 1) * 18 + k] = __float2half_rn(v.y);
            xs[(nb + 2) * 18 + k] = __float2half_rn(v.z);
            xs[(nb + 3) * 18 + k] = __float2half_rn(v.w);
        }
        // w tile: ws[o][k], k-contiguous
        {
            int oo = tid >> 2, k4 = (tid & 3) * 4;
            float4 v = *(const float4*)&w[(long)(o0 + oo) * CIN + kc + k4];
            __half2* wp = (__half2*)&ws[oo * 20 + k4];
            wp[0] = __floats2half2_rn(v.x, v.y);
            wp[1] = __floats2half2_rn(v.z, v.w);
        }
        __syncthreads();
        // single k16 MMA step
        uint32_t af[2][4], bf[8][2];
#pragma unroll
        for (int mt = 0; mt < 2; mt++) {
            int rb = wm * 32 + mt * 16 + lg;
            af[mt][0] = *(const uint32_t*)&ws[rb * 20 + 2 * lt];
            af[mt][1] = *(const uint32_t*)&ws[(rb + 8) * 20 + 2 * lt];
            af[mt][2] = *(const uint32_t*)&ws[rb * 20 + 2 * lt + 8];
            af[mt][3] = *(const uint32_t*)&ws[(rb + 8) * 20 + 2 * lt + 8];
        }
#pragma unroll
        for (int nt2 = 0; nt2 < 8; nt2++) {
            int nb = wn * 64 + nt2 * 8 + lg;
            bf[nt2][0] = *(const uint32_t*)&xs[nb * 18 + 2 * lt];
            bf[nt2][1] = *(const uint32_t*)&xs[nb * 18 + 2 * lt + 8];
        }
#pragma unroll
        for (int mt = 0; mt < 2; mt++)
#pragma unroll
            for (int nt2 = 0; nt2 < 8; nt2++)
                mma_f16(acc[mt][nt2][0], acc[mt][nt2][1],
                        acc[mt][nt2][2], acc[mt][nt2][3],
                        af[mt][0], af[mt][1], af[mt][2], af[mt][3],
                        bf[nt2][0], bf[nt2][1]);
    }
    float rs[2][2] = {{0.f, 0.f}, {0.f, 0.f}};
    float rq[2][2] = {{0.f, 0.f}, {0.f, 0.f}};
#pragma unroll
    for (int mt = 0; mt < 2; mt++) {
        int row0 = o0 + wm * 32 + mt * 16 + lg;
        int row1 = row0 + 8;
        float bv0 = bias[row0], bv1 = bias[row1];
#pragma unroll
        for (int nt2 = 0; nt2 < 8; nt2++) {
            int col = n0 + wn * 64 + nt2 * 8 + lt * 2;
            float v00 = acc[mt][nt2][0] + bv0, v01 = acc[mt][nt2][1] + bv0;
            float v10 = acc[mt][nt2][2] + bv1, v11 = acc[mt][nt2][3] + bv1;
            if (z == 0) {
                *(float2*)&out_cv0[((long)b * CM_ + row0) * N_ + col] = make_float2(v00, v01);
                *(float2*)&out_cv0[((long)b * CM_ + row1) * N_ + col] = make_float2(v10, v11);
            } else {
                *(__half2*)&out_sc[((long)b * CO_ + row0) * N_ + col] = __floats2half2_rn(v00, v01);
                *(__half2*)&out_sc[((long)b * CO_ + row1) * N_ + col] = __floats2half2_rn(v10, v11);
            }
            rs[mt][0] += v00 + v01; rq[mt][0] += v00 * v00 + v01 * v01;
            rs[mt][1] += v10 + v11; rq[mt][1] += v10 * v10 + v11 * v11;
        }
    }
#pragma unroll
    for (int mt = 0; mt < 2; mt++)
#pragma unroll
        for (int h = 0; h < 2; h++) {
#pragma unroll
            for (int off = 1; off <= 2; off <<= 1) {
                rs[mt][h] += __shfl_xor_sync(0xffffffffu, rs[mt][h], off);
                rq[mt][h] += __shfl_xor_sync(0xffffffffu, rq[mt][h], off);
            }
        }
    if (lt == 0) {
#pragma unroll
        for (int mt = 0; mt < 2; mt++)
#pragma unroll
            for (int h = 0; h < 2; h++) {
                int rl = wm * 32 + mt * 16 + lg + h * 8;
                sred[rl][wn] = rs[mt][h];
                qred[rl][wn] = rq[mt][h];
            }
    }
    __syncthreads();
    if (tid < 64) {
        float s = sred[tid][0] + sred[tid][1] + sred[tid][2] + sred[tid][3];
        float q = qred[tid][0] + qred[tid][1] + qred[tid][2] + qred[tid][3];
        int seg = blockIdx.y * 32 + nt;                      // 0..511
        long pi = ((long)(chbase + tid) * 512 + seg) * 2;
        spart[pi + 0] = s;
        spart[pi + 1] = q;
    }
}

// ---------------------------------------------------------------------------
// cv2: fp16 MMA; input hf fp16, relu(bn1) fused in, bn2 partials fused out.
// ---------------------------------------------------------------------------
__global__ void __launch_bounds__(256) pwconv_cv2_kernel(
    const __half* __restrict__ x, const float* __restrict__ w,
    const float* __restrict__ bias, float* __restrict__ out,
    const float* __restrict__ ns, const float* __restrict__ nt_,
    float* __restrict__ spart)
{
    constexpr int CIN = 64, BM = 64, BN = 256, BK = 16;
    __shared__ __half xs[BN * 18];
    __shared__ __half ws[BM * 20];
    __shared__ float sred[64][4], qred[64][4];
    const int bx = blockIdx.x;           // 0..31
    const int z  = bx & 3;
    const int ntile = bx >> 2;           // 0..7
    const int n0 = ntile * BN;
    const int b  = blockIdx.y;
    const int o0 = z * BM;
    const int tid  = threadIdx.x;
    const int lane = tid & 31, warp = tid >> 5;
    const int wm = warp >> 2, wn = warp & 3;
    const int lg = lane >> 2, lt = lane & 3;

    float acc[2][8][4];
#pragma unroll
    for (int i = 0; i < 2; i++)
#pragma unroll
        for (int j = 0; j < 8; j++)
#pragma unroll
            for (int u = 0; u < 4; u++) acc[i][j][u] = 0.f;

    for (int kc = 0; kc < CIN; kc += BK) {
        __syncthreads();
#pragma unroll
        for (int u = 0; u < 4; u++) {
            int vi = tid + u * 256;
            int k = vi >> 6, c4 = vi & 63;
            uint2 hv = *(const uint2*)&x[((long)b * CIN + kc + k) * S_ + n0 + c4 * 4];
            float2 f0 = __half22float2(*(const __half2*)&hv.x);
            float2 f1 = __half22float2(*(const __half2*)&hv.y);
            float sa = ns[kc + k], sb = nt_[kc + k];
            int nb = c4 * 4;
            xs[(nb + 0) * 18 + k] = __float2half_rn(fmaxf(f0.x * sa + sb, 0.f));
            xs[(nb + 1) * 18 + k] = __float2half_rn(fmaxf(f0.y * sa + sb, 0.f));
            xs[(nb + 2) * 18 + k] = __float2half_rn(fmaxf(f1.x * sa + sb, 0.f));
            xs[(nb + 3) * 18 + k] = __float2half_rn(fmaxf(f1.y * sa + sb, 0.f));
        }
        {
            int oo = tid >> 2, k4 = (tid & 3) * 4;
            float4 v = *(const float4*)&w[(long)(o0 + oo) * CIN + kc + k4];
            __half2* wp = (__half2*)&ws[oo * 20 + k4];
            wp[0] = __floats2half2_rn(v.x, v.y);
            wp[1] = __floats2half2_rn(v.z, v.w);
        }
        __syncthreads();
        uint32_t af[2][4], bf[8][2];
#pragma unroll
        for (int mt = 0; mt < 2; mt++) {
            int rb = wm * 32 + mt * 16 + lg;
            af[mt][0] = *(const uint32_t*)&ws[rb * 20 + 2 * lt];
            af[mt][1] = *(const uint32_t*)&ws[(rb + 8) * 20 + 2 * lt];
            af[mt][2] = *(const uint32_t*)&ws[rb * 20 + 2 * lt + 8];
            af[mt][3] = *(const uint32_t*)&ws[(rb + 8) * 20 + 2 * lt + 8];
        }
#pragma unroll
        for (int nt2 = 0; nt2 < 8; nt2++) {
            int nb = wn * 64 + nt2 * 8 + lg;
            bf[nt2][0] = *(const uint32_t*)&xs[nb * 18 + 2 * lt];
            bf[nt2][1] = *(const uint32_t*)&xs[nb * 18 + 2 * lt + 8];
        }
#pragma unroll
        for (int mt = 0; mt < 2; mt++)
#pragma unroll
            for (int nt2 = 0; nt2 < 8; nt2++)
                mma_f16(acc[mt][nt2][0], acc[mt][nt2][1],
                        acc[mt][nt2][2], acc[mt][nt2][3],
                        af[mt][0], af[mt][1], af[mt][2], af[mt][3],
                        bf[nt2][0], bf[nt2][1]);
    }
    float rs[2][2] = {{0.f, 0.f}, {0.f, 0.f}};
    float rq[2][2] = {{0.f, 0.f}, {0.f, 0.f}};
#pragma unroll
    for (int mt = 0; mt < 2; mt++) {
        int row0 = o0 + wm * 32 + mt * 16 + lg;
        int row1 = row0 + 8;
        float bv0 = bias[row0], bv1 = bias[row1];
#pragma unroll
        for (int nt2 = 0; nt2 < 8; nt2++) {
            int col = n0 + wn * 64 + nt2 * 8 + lt * 2;
            float v00 = acc[mt][nt2][0] + bv0, v01 = acc[mt][nt2][1] + bv0;
            float v10 = acc[mt][nt2][2] + bv1, v11 = acc[mt][nt2][3] + bv1;
            *(float2*)&out[((long)b * CO_ + row0) * S_ + col] = make_float2(v00, v01);
            *(float2*)&out[((long)b * CO_ + row1) * S_ + col] = make_float2(v10, v11);
            rs[mt][0] += v00 + v01; rq[mt][0] += v00 * v00 + v01 * v01;
            rs[mt][1] += v10 + v11; rq[mt][1] += v10 * v10 + v11 * v11;
        }
    }
#pragma unroll
    for (int mt = 0; mt < 2; mt++)
#pragma unroll
        for (int h = 0; h < 2; h++) {
#pragma unroll
            for (int off = 1; off <= 2; off <<= 1) {
                rs[mt][h] += __shfl_xor_sync(0xffffffffu, rs[mt][h], off);
                rq[mt][h] += __shfl_xor_sync(0xffffffffu, rq[mt][h], off);
            }
        }
    if (lt == 0) {
#pragma unroll
        for (int mt = 0; mt < 2; mt++)
#pragma unroll
            for (int h = 0; h < 2; h++) {
                int rl = wm * 32 + mt * 16 + lg + h * 8;
                sred[rl][wn] = rs[mt][h];
                qred[rl][wn] = rq[mt][h];
            }
    }
    __syncthreads();
    if (tid < 64) {
        float s = sred[tid][0] + sred[tid][1] + sred[tid][2] + sred[tid][3];
        float q = qred[tid][0] + qred[tid][1] + qred[tid][2] + qred[tid][3];
        int seg = blockIdx.y * 8 + ntile;               // 0..127
        long pi = ((long)(o0 + tid) * 128 + seg) * 2;
        spart[pi + 0] = s;
        spart[pi + 1] = q;
    }
}

// ---------------------------------------------------------------------------
// FKA GEMM (fp16 MMA): hf16[b,o,s] = sum_{r<1024} cv_w[o,r]*agg_fp16[b,s,r]
// xs[s][r] stride 34 halves; ws[o][r] stride 34 halves (per 32-wide chunk).
// ---------------------------------------------------------------------------
__global__ void __launch_bounds__(256) fka_gemm_mma_kernel(
    const __half* __restrict__ A, const float* __restrict__ W,
    __half* __restrict__ out, float* __restrict__ spart)
{
    constexpr int BN = 128, BK = 32;
    __shared__ __half xs[BN * 34];
    __shared__ __half ws[64 * 34];
    __shared__ float sred[64][4], qred[64][4];
    const int s0 = blockIdx.x * BN;
    const int b  = blockIdx.y;
    const int tid  = threadIdx.x;
    const int lane = tid & 31, warp = tid >> 5;
    const int wm = warp >> 2, wn = warp & 3;
    const int lg = lane >> 2, lt = lane & 3;
    const uint32_t* Au = (const uint32_t*)(A + ((long)b * S_ + s0) * 1024);

    float acc[2][4][4];
#pragma unroll
    for (int i = 0; i < 2; i++)
#pragma unroll
        for (int j = 0; j < 4; j++)
#pragma unroll
            for (int u = 0; u < 4; u++) acc[i][j][u] = 0.f;

    const int as  = tid >> 1;             // s index 0..127
    const int ar0 = (tid & 1) * 16;       // r offset within chunk

    for (int rc = 0; rc < 1024; rc += BK) {
        __syncthreads();
        // A tile: fp16 passthrough, 16 halves per thread
        {
            const uint4* src = (const uint4*)&Au[(long)as * 512 + (rc >> 1) + (ar0 >> 1)];
            uint4 v0 = src[0];
            uint4 v1 = src[1];
            uint32_t* dst = (uint32_t*)&xs[as * 34 + ar0];
            dst[0] = v0.x; dst[1] = v0.y; dst[2] = v0.z; dst[3] = v0.w;
            dst[4] = v1.x; dst[5] = v1.y; dst[6] = v1.z; dst[7] = v1.w;
        }
        // W tile: 64 o x 32 r fp32 -> fp16, r-contiguous
#pragma unroll
        for (int vi = tid; vi < 512; vi += 256) {
            int o = vi >> 3, r4 = (vi & 7) * 4;
            float4 v = *(const float4*)&W[(long)o * 1024 + rc + r4];
            uint32_t* wp = (uint32_t*)&ws[o * 34 + r4];
            __half2 h0v = __floats2half2_rn(v.x, v.y);
            __half2 h1v = __floats2half2_rn(v.z, v.w);
            wp[0] = *(uint32_t*)&h0v;
            wp[1] = *(uint32_t*)&h1v;
        }
        __syncthreads();
#pragma unroll
        for (int kt = 0; kt < BK; kt += 16) {
            uint32_t af[2][4], bf[4][2];
#pragma unroll
            for (int mt = 0; mt < 2; mt++) {
                int rb = wm * 32 + mt * 16 + lg;
                af[mt][0] = *(const uint32_t*)&ws[rb * 34 + kt + 2 * lt];
                af[mt][1] = *(const uint32_t*)&ws[(rb + 8) * 34 + kt + 2 * lt];
                af[mt][2] = *(const uint32_t*)&ws[rb * 34 + kt + 2 * lt + 8];
                af[mt][3] = *(const uint32_t*)&ws[(rb + 8) * 34 + kt + 2 * lt + 8];
            }
#pragma unroll
            for (int nt2 = 0; nt2 < 4; nt2++) {
                int nb = wn * 32 + nt2 * 8 + lg;
                bf[nt2][0] = *(const uint32_t*)&xs[nb * 34 + kt + 2 * lt];
                bf[nt2][1] = *(const uint32_t*)&xs[nb * 34 + kt + 2 * lt + 8];
            }
#pragma unroll
            for (int mt = 0; mt < 2; mt++)
#pragma unroll
                for (int nt2 = 0; nt2 < 4; nt2++)
                    mma_f16(acc[mt][nt2][0], acc[mt][nt2][1],
                            acc[mt][nt2][2], acc[mt][nt2][3],
                            af[mt][0], af[mt][1], af[mt][2], af[mt][3],
                            bf[nt2][0], bf[nt2][1]);
        }
    }
    // epilogue (fp16 out) + fused bn1 partials (fp32 accs)
    float rs[2][2] = {{0.f, 0.f}, {0.f, 0.f}};
    float rq[2][2] = {{0.f, 0.f}, {0.f, 0.f}};
#pragma unroll
    for (int mt = 0; mt < 2; mt++) {
        int row0 = wm * 32 + mt * 16 + lg;
        int row1 = row0 + 8;
#pragma unroll
        for (int nt2 = 0; nt2 < 4; nt2++) {
            int col = s0 + wn * 32 + nt2 * 8 + lt * 2;
            float v00 = acc[mt][nt2][0], v01 = acc[mt][nt2][1];
            float v10 = acc[mt][nt2][2], v11 = acc[mt][nt2][3];
            *(__half2*)&out[((long)b * 64 + row0) * S_ + col] = __floats2half2_rn(v00, v01);
            *(__half2*)&out[((long)b * 64 + row1) * S_ + col] = __floats2half2_rn(v10, v11);
            rs[mt][0] += v00 + v01; rq[mt][0] += v00 * v00 + v01 * v01;
            rs[mt][1] += v10 + v11; rq[mt][1] += v10 * v10 + v11 * v11;
        }
    }
#pragma unroll
    for (int mt = 0; mt < 2; mt++)
#pragma unroll
        for (int h = 0; h < 2; h++) {
#pragma unroll
            for (int off = 1; off <= 2; off <<= 1) {
                rs[mt][h] += __shfl_xor_sync(0xffffffffu, rs[mt][h], off);
                rq[mt][h] += __shfl_xor_sync(0xffffffffu, rq[mt][h], off);
            }
        }
    if (lt == 0) {
#pragma unroll
        for (int mt = 0; mt < 2; mt++)
#pragma unroll
            for (int h = 0; h < 2; h++) {
                int rl = wm * 32 + mt * 16 + lg + h * 8;
                sred[rl][wn] = rs[mt][h];
                qred[rl][wn] = rq[mt][h];
            }
    }
    __syncthreads();
    if (tid < 64) {
        float s = sred[tid][0] + sred[tid][1] + sred[tid][2] + sred[tid][3];
        float q = qred[tid][0] + qred[tid][1] + qred[tid][2] + qred[tid][3];
        int nseg = gridDim.x * gridDim.y;               // 256
        int seg  = blockIdx.y * gridDim.x + blockIdx.x;
        long pi = ((long)tid * nseg + seg) * 2;
        spart[pi + 0] = s;
        spart[pi + 1] = q;
    }
}

// ---------------------------------------------------------------------------
// Stats finalize
// ---------------------------------------------------------------------------
__global__ void __launch_bounds__(128) stats_final_kernel(
    const float* __restrict__ partial, int nseg, float M,
    const float* __restrict__ g, const float* __restrict__ bb, int gmod,
    float* __restrict__ scale, float* __restrict__ shift)
{
    const int c = blockIdx.x;
    float ls = 0.f, lq = 0.f;
    for (int i = threadIdx.x; i < nseg; i += 128) {
        ls += partial[(c * nseg + i) * 2 + 0];
        lq += partial[(c * nseg + i) * 2 + 1];
    }
#pragma unroll
    for (int off = 16; off; off >>= 1) {
        ls += __shfl_xor_sync(0xffffffffu, ls, off);
        lq += __shfl_xor_sync(0xffffffffu, lq, off);
    }
    __shared__ float sh[8];
    const int wid = threadIdx.x >> 5, lane = threadIdx.x & 31;
    if (lane == 0) { sh[wid] = ls; sh[4 + wid] = lq; }
    __syncthreads();
    if (threadIdx.x == 0) {
        float ts = sh[0] + sh[1] + sh[2] + sh[3];
        float tq = sh[4] + sh[5] + sh[6] + sh[7];
        float mean = ts / M;
        float var  = tq / M - mean * mean;
        float sc = g[c % gmod] * rsqrtf(var + 1e-5f);
        scale[c] = sc;
        shift[c] = bb[c % gmod] - mean * sc;
    }
}

// ---------------------------------------------------------------------------
// Merged finals: bn0 (blk 0..63), bnsc (64..319) over 512 segs,
// in1-from-moments (320..575)
// ---------------------------------------------------------------------------
__global__ void __launch_bounds__(128) finals_merged_kernel(
    const float* __restrict__ part, const float* __restrict__ pm,
    const float* __restrict__ w1,
    const float* __restrict__ bn0_g, const float* __restrict__ bn0_b,
    const float* __restrict__ bnsc_g, const float* __restrict__ bnsc_b,
    const float* __restrict__ in1_g, const float* __restrict__ in1_b,
    float* __restrict__ aff)
{
    const int blk = blockIdx.x;
    if (blk < 320) {
        const int c = blk;
        float ls = 0.f, lq = 0.f;
        for (int i = threadIdx.x; i < 512; i += 128) {
            ls += part[(c * 512 + i) * 2 + 0];
            lq += part[(c * 512 + i) * 2 + 1];
        }
#pragma unroll
        for (int off = 16; off; off >>= 1) {
            ls += __shfl_xor_sync(0xffffffffu, ls, off);
            lq += __shfl_xor_sync(0xffffffffu, lq, off);
        }
        __shared__ float sh[8];
        const int wid = threadIdx.x >> 5, lane = threadIdx.x & 31;
        if (lane == 0) { sh[wid] = ls; sh[4 + wid] = lq; }
        __syncthreads();
        if (threadIdx.x == 0) {
            float ts = sh[0] + sh[1] + sh[2] + sh[3];
            float tq = sh[4] + sh[5] + sh[6] + sh[7];
            float M = (float)B_ * (float)N_;
            float mean = ts / M;
            float var  = tq / M - mean * mean;
            if (c < 64) {
                float sc = bn0_g[c] * rsqrtf(var + 1e-5f);
                aff[OFF_SCALE0 + c] = sc;
                aff[OFF_SHIFT0 + c] = bn0_b[c] - mean * sc;
            } else {
                int cc = c - 64;
                float sc = bnsc_g[cc] * rsqrtf(var + 1e-5f);
                aff[OFF_SCALESC + cc] = sc;
                aff[OFF_SHIFTSC + cc] = bnsc_b[cc] - mean * sc;
            }
        }
    } else {
        const int bq = blk - 320;
        const int b = bq >> 4, q = bq & 15;
        if (threadIdx.x < 32) {
            const int lane = threadIdx.x;
            float v = 0.f;
            if (lane < 9)
                for (int i = 0; i < 8; i++) v += pm[(b * 8 + i) * 9 + lane];
            float m[9];
#pragma unroll
            for (int j = 0; j < 9; j++) m[j] = __shfl_sync(0xffffffffu, v, j);
            if (lane == 0) {
                const float Mv = (float)SK_;
                float w0 = w1[q * 3 + 0], wa = w1[q * 3 + 1], wb = w1[q * 3 + 2];
                float mu = (w0 * m[0] + wa * m[1] + wb * m[2]) / Mv;
                float e2 = (w0 * w0 * m[3] + 2.f * w0 * wa * m[4] + 2.f * w0 * wb * m[5]
                          + wa * wa * m[6] + 2.f * wa * wb * m[7] + wb * wb * m[8]) / Mv;
                float var = e2 - mu * mu;
                float sc = in1_g[q] * rsqrtf(var + 1e-5f);
                aff[OFF_IN1SC + bq] = sc;
                aff[OFF_IN1SH + bq] = in1_b[q] - mu * sc;
            }
        }
    }
}

// ---------------------------------------------------------------------------
// Normalize+relu h0 and transpose to (B,N,64) fp16; 64x64 tiles
// ---------------------------------------------------------------------------
__global__ void __launch_bounds__(256) transpose_norm_kernel(
    const float* __restrict__ in, __half* __restrict__ outT,
    const float* __restrict__ scale, const float* __restrict__ shift)
{
    __shared__ float t[64][65];
    const int n0 = blockIdx.x * 64;
    const int b  = blockIdx.y;
    const int tid = threadIdx.x;
#pragma unroll
    for (int i = tid; i < 1024; i += 256) {
        int c = i >> 4, n4 = (i & 15) * 4;
        float4 v = *(const float4*)&in[((long)b * 64 + c) * N_ + n0 + n4];
        float sa = scale[c], sb = shift[c];
        t[c][n4 + 0] = fmaxf(v.x * sa + sb, 0.f);
        t[c][n4 + 1] = fmaxf(v.y * sa + sb, 0.f);
        t[c][n4 + 2] = fmaxf(v.z * sa + sb, 0.f);
        t[c][n4 + 3] = fmaxf(v.w * sa + sb, 0.f);
    }
    __syncthreads();
#pragma unroll
    for (int i = tid; i < 1024; i += 256) {
        int n = i >> 4, c4 = (i & 15) * 4;
        __half2 h0v = __floats2half2_rn(t[c4][n], t[c4 + 1][n]);
        __half2 h1v = __floats2half2_rn(t[c4 + 2][n], t[c4 + 3][n]);
        uint2 u = make_uint2(*(uint32_t*)&h0v, *(uint32_t*)&h1v);
        *(uint2*)&outT[((long)b * N_ + n0 + n) * 64 + c4] = u;
    }
}

// ---------------------------------------------------------------------------
// FKA prep: local coords p + dw, per-block p-moment partials
// ---------------------------------------------------------------------------
__global__ void __launch_bounds__(256) fka_prep_kernel(
    const float* __restrict__ pos, const float* __restrict__ sup,
    const int* __restrict__ idx, const float* __restrict__ alpha,
    const float* __restrict__ beta, const float* __restrict__ nr,
    float* __restrict__ p, float* __restrict__ dw, float* __restrict__ pm)
{
    int t = blockIdx.x * blockDim.x + threadIdx.x;
    int b = t / S_, s = t % S_;
    float a = alpha[0], be = beta[0], inr = 1.f / nr[0];
    float sx = sup[((long)b * 3 + 0) * S_ + s];
    float sy = sup[((long)b * 3 + 1) * S_ + s];
    float sz = sup[((long)b * 3 + 2) * S_ + s];
    float dwl[K_];
    float sum = 0.f;
    float mm[9];
#pragma unroll
    for (int j = 0; j < 9; j++) mm[j] = 0.f;
#pragma unroll
    for (int k = 0; k < K_; k++) {
        int id = idx[(long)t * K_ + k];
        float px = pos[((long)b * 3 + 0) * N_ + id] - sx;
        float py = pos[((long)b * 3 + 1) * N_ + id] - sy;
        float pz = pos[((long)b * 3 + 2) * N_ + id] - sz;
        float d = sqrtf(px * px + py * py + pz * pz);
        float wv = 1.f / (1.f + expf(a * d - be));
        dwl[k] = wv; sum += wv;
        float n0v = px * inr, n1v = py * inr, n2v = pz * inr;
        long eb = (long)s * K_ + k;
        p[((long)b * 3 + 0) * SK_ + eb] = n0v;
        p[((long)b * 3 + 1) * SK_ + eb] = n1v;
        p[((long)b * 3 + 2) * SK_ + eb] = n2v;
        mm[0] += n0v; mm[1] += n1v; mm[2] += n2v;
        mm[3] += n0v * n0v; mm[4] += n0v * n1v; mm[5] += n0v * n2v;
        mm[6] += n1v * n1v; mm[7] += n1v * n2v; mm[8] += n2v * n2v;
    }
    sum = sum + (sum == 0.f ? 1.f : 0.f) + 1e-6f;
    float f = (float)K_ / sum;
#pragma unroll
    for (int k = 0; k < K_; k++) dw[(long)t * K_ + k] = dwl[k] * f;

    __shared__ float sm[8][9];
    const int wid = threadIdx.x >> 5, lane = threadIdx.x & 31;
#pragma unroll
    for (int j = 0; j < 9; j++) {
        float v = mm[j];
#pragma unroll
        for (int off = 16; off; off >>= 1)
            v += __shfl_xor_sync(0xffffffffu, v, off);
        if (lane == 0) sm[wid][j] = v;
    }
    __syncthreads();
    if (threadIdx.x < 9) {
        float v = 0.f;
#pragma unroll
        for (int w = 0; w < 8; w++) v += sm[w][threadIdx.x];
        pm[blockIdx.x * 9 + threadIdx.x] = v;
    }
}

// ---------------------------------------------------------------------------
// Stage 2 (stats only): z1 on the fly; z2 computed but NOT stored;
// emits IN2 stats partials.
// ---------------------------------------------------------------------------
__global__ void __launch_bounds__(256) fc_stage2_kernel(
    const float* __restrict__ p, const float* __restrict__ w1,
    const float* __restrict__ w2,
    const float* __restrict__ sc1, const float* __restrict__ sh1,
    const float* __restrict__ dw, float* __restrict__ spart)
{
    __shared__ float w2s[16 * 32];
    __shared__ float w1s[48];
    __shared__ float scs[16], shs[16];
    __shared__ float sred[8][16], qred[8][16];
    const int tid = threadIdx.x;
    const int b = blockIdx.x >> 7;
    const int s0 = (blockIdx.x & 127) * 16;
    const int g = tid >> 4, lane = tid & 15;
    const int warp = tid >> 5, wlane = tid & 31;
    const int s = s0 + g;

    w2s[tid] = w2[tid];
    w2s[tid + 256] = w2[tid + 256];
    if (tid < 48) w1s[tid] = w1[tid];
    if (tid < 16) { scs[tid] = sc1[b * 16 + tid]; shs[tid] = sh1[b * 16 + tid]; }
    __syncthreads();

    const long e = (long)s * K_ + lane;
    const float p0 = p[((long)b * 3 + 0) * SK_ + e];
    const float p1 = p[((long)b * 3 + 1) * SK_ + e];
    const float p2 = p[((long)b * 3 + 2) * SK_ + e];
    const float dwk = dw[((long)b * S_ + s) * K_ + lane];
    float m[32];
#pragma unroll
    for (int q = 0; q < 16; q++) {
        float z = w1s[q * 3 + 0] * p0 + w1s[q * 3 + 1] * p1 + w1s[q * 3 + 2] * p2;
        float v = fmaxf(z * scs[q] + shs[q], 0.f);
        m[q] = v;
        float md = v * dwk;
#pragma unroll
        for (int off = 8; off; off >>= 1)
            md = fmaxf(md, __shfl_xor_sync(0xffffffffu, md, off, 16));
        m[16 + q] = md;
    }
#pragma unroll
    for (int q2 = 0; q2 < 16; q2++) {
        float acc = 0.f;
#pragma unroll
        for (int c = 0; c < 32; c++) acc += w2s[q2 * 32 + c] * m[c];
        float a1 = acc, a2 = acc * acc;
#pragma unroll
        for (int off = 16; off; off >>= 1) {
            a1 += __shfl_xor_sync(0xffffffffu, a1, off);
            a2 += __shfl_xor_sync(0xffffffffu, a2, off);
        }
        if (wlane == 0) { sred[warp][q2] = a1; qred[warp][q2] = a2; }
    }
    __syncthreads();
    if (tid < 16) {
        float s1 = 0.f, s2 = 0.f;
#pragma unroll
        for (int w = 0; w < 8; w++) { s1 += sred[w][tid]; s2 += qred[w][tid]; }
        int ch = b * 16 + tid;
        int seg = blockIdx.x & 127;
        spart[(ch * 128 + seg) * 2 + 0] = s1;
        spart[(ch * 128 + seg) * 2 + 1] = s2;
    }
}

// ---------------------------------------------------------------------------
// Stage 3 + aggregation (recomputes z1/z2 from p, bit-exact vs stage 2)
// fp16 h0t gather, fp16 agg output.
// ---------------------------------------------------------------------------
__global__ void __launch_bounds__(256) fc_stage3_agg_kernel(
    const float* __restrict__ p, const float* __restrict__ w1,
    const float* __restrict__ w2, const float* __restrict__ w3,
    const float* __restrict__ sc1, const float* __restrict__ sh1,
    const float* __restrict__ sc2, const float* __restrict__ sh2,
    const float* __restrict__ dw, const int* __restrict__ idx,
    const __half* __restrict__ h0t, __half* __restrict__ agg)
{
    __shared__ float w2s[512];
    __shared__ float w3s[512];
    __shared__ float w1s[48];
    __shared__ float sc1s[16], sh1s[16], sc2s[16], sh2s[16];
    __shared__ float smat[16][16][16];   // [group][q][k]
    __shared__ int   sidx[16][16];
    const int tid = threadIdx.x;
    const int b = blockIdx.x >> 7;
    const int s0 = (blockIdx.x & 127) * 16;
    const int g = tid >> 4, lane = tid & 15;
    const int s = s0 + g;

    w2s[tid] = w2[tid];
    w2s[tid + 256] = w2[tid + 256];
    w3s[tid] = w3[tid];
    w3s[tid + 256] = w3[tid + 256];
    if (tid < 48) w1s[tid] = w1[tid];
    if (tid < 16) {
        sc1s[tid] = sc1[b * 16 + tid]; sh1s[tid] = sh1[b * 16 + tid];
        sc2s[tid] = sc2[b * 16 + tid]; sh2s[tid] = sh2[b * 16 + tid];
    }
    __syncthreads();

    const long e = (long)s * K_ + lane;
    const float p0 = p[((long)b * 3 + 0) * SK_ + e];
    const float p1 = p[((long)b * 3 + 1) * SK_ + e];
    const float p2 = p[((long)b * 3 + 2) * SK_ + e];
    const float dwk = dw[((long)b * S_ + s) * K_ + lane];
    sidx[g][lane] = idx[((long)b * S_ + s) * K_ + lane];

    float m1[32];
#pragma unroll
    for (int q = 0; q < 16; q++) {
        float z = w1s[q * 3 + 0] * p0 + w1s[q * 3 + 1] * p1 + w1s[q * 3 + 2] * p2;
        float v = fmaxf(z * sc1s[q] + sh1s[q], 0.f);
        m1[q] = v;
        float md = v * dwk;
#pragma unroll
        for (int off = 8; off; off >>= 1)
            md = fmaxf(md, __shfl_xor_sync(0xffffffffu, md, off, 16));
        m1[16 + q] = md;
    }
    float m2[32];
#pragma unroll
    for (int q2 = 0; q2 < 16; q2++) {
        float acc = 0.f;
#pragma unroll
        for (int c = 0; c < 32; c++) acc += w2s[q2 * 32 + c] * m1[c];
        float v = fmaxf(acc * sc2s[q2] + sh2s[q2], 0.f);
        m2[q2] = v;
        float md = v * dwk;
#pragma unroll
        for (int off = 8; off; off >>= 1)
            md = fmaxf(md, __shfl_xor_sync(0xffffffffu, md, off, 16));
        m2[16 + q2] = md;
    }
#pragma unroll
    for (int q3 = 0; q3 < 16; q3++) {
        float acc = 0.f;
#pragma unroll
        for (int c = 0; c < 32; c++) acc += w3s[q3 * 32 + c] * m2[c];
        smat[g][q3][lane] = fmaxf(acc, 0.f) * dwk;
    }
    __syncwarp();

    float acc2[4][16];
#pragma unroll
    for (int cu = 0; cu < 4; cu++)
#pragma unroll
        for (int q = 0; q < 16; q++) acc2[cu][q] = 0.f;

#pragma unroll
    for (int k = 0; k < 16; k++) {
        int id = sidx[g][k];
        uint2 hv = *(const uint2*)(h0t + ((long)b * N_ + id) * 64 + lane * 4);
        float2 f0 = __half22float2(*(const __half2*)&hv.x);
        float2 f1 = __half22float2(*(const __half2*)&hv.y);
#pragma unroll
        for (int q = 0; q < 16; q++) {
            float mv = smat[g][q][k];
            acc2[0][q] += f0.x * mv;
            acc2[1][q] += f0.y * mv;
            acc2[2][q] += f1.x * mv;
            acc2[3][q] += f1.y * mv;
        }
    }
    uint32_t* aggu = (uint32_t*)agg;
    long base = ((long)b * S_ + s) * 512 + lane * 32;
#pragma unroll
    for (int cu = 0; cu < 4; cu++) {
        uint32_t pk[8];
#pragma unroll
        for (int qq = 0; qq < 8; qq++) {
            __half2 h2 = __floats2half2_rn(acc2[cu][qq * 2], acc2[cu][qq * 2 + 1]);
            pk[qq] = *(uint32_t*)&h2;
        }
        *(uint4*)&aggu[base + cu * 8 + 0] = make_uint4(pk[0], pk[1], pk[2], pk[3]);
        *(uint4*)&aggu[base + cu * 8 + 4] = make_uint4(pk[4], pk[5], pk[6], pk[7]);
    }
}

// ---------------------------------------------------------------------------
// Final fuse: out[b,o,s] = relu( bn2(y2)[b,o,s] + bnsc(gather-max sc16) )
// ---------------------------------------------------------------------------
__global__ void __launch_bounds__(256) final_fuse_kernel(
    const float* __restrict__ y2, const __half* __restrict__ ysc,
    const int* __restrict__ idx, const float* __restrict__ s2,
    const float* __restrict__ t2, const float* __restrict__ ssc,
    const float* __restrict__ tsc, float* __restrict__ out)
{
    __shared__ __half row[N_];
    const int o = blockIdx.x, b = blockIdx.y;
    const __half* src = ysc + ((long)b * CO_ + o) * N_;
    {
        const uint4* s4 = (const uint4*)src;
        uint4* d4 = (uint4*)row;
        for (int i = threadIdx.x; i < 1024; i += 256) d4[i] = s4[i];
    }
    __syncthreads();
    const float sa = ssc[o], sb = tsc[o];
    const float ha = s2[o],  hb = t2[o];
    const int* ib = idx + (long)b * S_ * K_;
    const float* y2b = y2 + ((long)b * CO_ + o) * S_;
    float* ob = out + ((long)b * CO_ + o) * S_;
    for (int s = threadIdx.x; s < S_; s += 256) {
        const int4* ip = (const int4*)(ib + s * K_);
        float mx = -1e30f, mn = 1e30f;
#pragma unroll
        for (int kk = 0; kk < 4; kk++) {
            int4 v = ip[kk];
            float a = __half2float(row[v.x]);
            float c = __half2float(row[v.y]);
            float d = __half2float(row[v.z]);
            float e = __half2float(row[v.w]);
            mx = fmaxf(fmaxf(fmaxf(mx, a), fmaxf(c, d)), e);
            mn = fminf(fminf(fminf(mn, a), fminf(c, d)), e);
        }
        float scv = (sa >= 0.f) ? (sa * mx + sb) : (sa * mn + sb);
        ob[s] = fmaxf(y2b[s] * ha + hb + scv, 0.f);
    }
}

// ---------------------------------------------------------------------------
// Host launcher
// ---------------------------------------------------------------------------
extern "C" void kernel_launch(void* const* d_in, const int* in_sizes, int n_in,
                              void* d_out, int out_size)
{
    const float* x      = (const float*)d_in[0];
    const float* pos    = (const float*)d_in[1];
    const float* sup    = (const float*)d_in[2];
    const int*   idx    = (const int*)  d_in[3];
    // d_in[4] = mask_indices (unused)
    const float* cv0_w  = (const float*)d_in[5];
    const float* cv0_b  = (const float*)d_in[6];
    const float* bn0_g  = (const float*)d_in[7];
    const float* bn0_b  = (const float*)d_in[8];
    const float* fc1_w  = (const float*)d_in[9];
    const float* fc2_w  = (const float*)d_in[10];
    const float* fc3_w  = (const float*)d_in[11];
    const float* in1_g  = (const float*)d_in[12];
    const float* in1_b  = (const float*)d_in[13];
    const float* in2_g  = (const float*)d_in[14];
    const float* in2_b  = (const float*)d_in[15];
    const float* alpha  = (const float*)d_in[16];
    const float* beta   = (const float*)d_in[17];
    const float* nrad   = (const float*)d_in[18];
    const float* cv_w   = (const float*)d_in[19];
    const float* bn1_g  = (const float*)d_in[20];
    const float* bn1_b  = (const float*)d_in[21];
    const float* cv2_w  = (const float*)d_in[22];
    const float* cv2_b  = (const float*)d_in[23];
    const float* bn2_g  = (const float*)d_in[24];
    const float* bn2_b  = (const float*)d_in[25];
    const float* sc_w   = (const float*)d_in[26];
    const float* sc_b   = (const float*)d_in[27];
    const float* bnsc_g = (const float*)d_in[28];
    const float* bnsc_b = (const float*)d_in[29];
    float* out = (float*)d_out;

    float *p_h0, *p_p, *p_dw, *p_y2, *p_aff, *p_part, *p_pm;
    __half *p_h0t, *p_agg, *p_sc, *p_hf;
    cudaGetSymbolAddress((void**)&p_h0,  g_h0);
    cudaGetSymbolAddress((void**)&p_h0t, g_h0t);
    cudaGetSymbolAddress((void**)&p_sc,  g_sc);
    cudaGetSymbolAddress((void**)&p_p,   g_p);
    cudaGetSymbolAddress((void**)&p_dw,  g_dw);
    cudaGetSymbolAddress((void**)&p_agg, g_agg);
    cudaGetSymbolAddress((void**)&p_hf,  g_hf);
    cudaGetSymbolAddress((void**)&p_y2,  g_y2);
    cudaGetSymbolAddress((void**)&p_aff, g_aff);
    cudaGetSymbolAddress((void**)&p_part, g_part);
    cudaGetSymbolAddress((void**)&p_pm,  g_pm);

    // 1) cv0 (fp32) + shortcut (fp16) convs (fp16 MMA)
    pwconv_dual_kernel<<<dim3(160, B_), 256>>>(
        x, cv0_w, cv0_b, sc_w, sc_b, p_h0, p_sc, p_part + PART_ALL);

    // 2) FKA geometry prep (+ p-moment partials)
    fka_prep_kernel<<<(B_ * S_) / 256, 256>>>(pos, sup, idx, alpha, beta, nrad,
                                              p_p, p_dw, p_pm);

    // 3) merged finals: bn0, bnsc, IN1-from-moments
    finals_merged_kernel<<<576, 128>>>(p_part + PART_ALL, p_pm, fc1_w,
        bn0_g, bn0_b, bnsc_g, bnsc_b, in1_g, in1_b, p_aff);

    // 4) normalize+relu+transpose h0 -> (B,N,64) fp16
    transpose_norm_kernel<<<dim3(N_/64, B_), 256>>>(
        p_h0, p_h0t, p_aff + OFF_SCALE0, p_aff + OFF_SHIFT0);

    // 5) stage 2 (stats-only)
    fc_stage2_kernel<<<(B_ * S_) / 16, 256>>>(p_p, fc1_w, fc2_w,
        p_aff + OFF_IN1SC, p_aff + OFF_IN1SH, p_dw, p_part + PART_Z2);
    stats_final_kernel<<<256, 128>>>(p_part + PART_Z2, 128, (float)SK_,
        in2_g, in2_b, Q_, p_aff + OFF_IN2SC, p_aff + OFF_IN2SH);

    // 6) stage 3 + aggregation (fp16 h0t gather, fp16 agg)
    fc_stage3_agg_kernel<<<(B_ * S_) / 16, 256>>>(p_p, fc1_w, fc2_w, fc3_w,
        p_aff + OFF_IN1SC, p_aff + OFF_IN1SH,
        p_aff + OFF_IN2SC, p_aff + OFF_IN2SH, p_dw, idx, p_h0t, p_agg);

    // 7) final FKA contraction (fp16 MMA) + fused bn1 partials
    fka_gemm_mma_kernel<<<dim3(S_/128, B_), 256>>>(p_agg, cv_w, p_hf,
        p_part + PART_HF);
    stats_final_kernel<<<CM_, 128>>>(p_part + PART_HF, 256, (float)(B_ * S_),
        bn1_g, bn1_b, CM_, p_aff + OFF_SCALE1, p_aff + OFF_SHIFT1);

    // 8) cv2 (fp16 MMA, fp16 hf input)
    pwconv_cv2_kernel<<<dim3(32, B_), 256>>>(
        p_hf, cv2_w, cv2_b, p_y2, p_aff + OFF_SCALE1, p_aff + OFF_SHIFT1,
        p_part + PART_Y2);
    stats_final_kernel<<<CO_, 128>>>(p_part + PART_Y2, 128, (float)(B_ * S_),
        bn2_g, bn2_b, CO_, p_aff + OFF_SCALE2, p_aff + OFF_SHIFT2);

    // 9) final fuse
    final_fuse_kernel<<<dim3(CO_, B_), 256>>>(p_y2, p_sc, idx,
        p_aff + OFF_SCALE2, p_aff + OFF_SHIFT2,
        p_aff + OFF_SCALESC, p_aff + OFF_SHIFTSC, out);
}